// round 16
// baseline (speedup 1.0000x reference)
#include <cuda_runtime.h>
#include <cuda_bf16.h>
#include <cstdint>
#include <stdint.h>
#include <math.h>

#define BATCH 32
#define SEQL 1024
#define CIN 21
#define DMODEL 512
#define DFF 2048
#define NLAYERS 3
#define TOPK 6
#define NCLS 10
#define BL (BATCH*SEQL)        // 32768
#define LD (SEQL*DMODEL)       // 524288

typedef __nv_bfloat16 bf16;

// ---------------- scratch ----------------
__device__ float g_x[BL*DMODEL];
__device__ float g_q[BL*DMODEL];               // y (corr path) / LN output later
__device__ float g_k[BL*DMODEL];               // final gelu-masked output
__device__ float g_qT[BL*DMODEL];
__device__ float g_kT[BL*DMODEL];
__device__ float g_tmp[BL*DMODEL];
__device__ bf16  g_cvA[(size_t)BL*1024];        // act pair [M][hi 512 | lo 512]
__device__ bf16  g_cvH[(size_t)BL*4096];        // FFN1 out pair [M][hi 2048 | lo 2048]
__device__ bf16  g_cvB[(size_t)2048*2048];      // weight pairs (sub-allocated)
__device__ float2 g_Spart[BATCH*32*SEQL];
__device__ float2 g_S[BATCH*SEQL];
__device__ float g_mv[BATCH*SEQL];
__device__ float g_w6[BATCH*TOPK];
__device__ int   g_d6[BATCH*TOPK];
__device__ float g_colmean[BATCH*DMODEL];
__device__ float g_part[64*NCLS*8*BATCH];

// ---------------- helpers ----------------
__device__ __forceinline__ uint32_t smem_u32(const void* p) {
    uint32_t a;
    asm("{ .reg .u64 t; cvta.to.shared.u64 t, %1; cvt.u32.u64 %0, t; }" : "=r"(a) : "l"(p));
    return a;
}
__device__ __forceinline__ void cp16(uint32_t s, const void* g) {
    asm volatile("cp.async.cg.shared.global [%0], [%1], 16;" :: "r"(s), "l"(g));
}
__device__ __forceinline__ void ldmx4(uint32_t& r0, uint32_t& r1, uint32_t& r2, uint32_t& r3, uint32_t a) {
    asm volatile("ldmatrix.sync.aligned.m8n8.x4.shared.b16 {%0,%1,%2,%3}, [%4];"
                 : "=r"(r0), "=r"(r1), "=r"(r2), "=r"(r3) : "r"(a));
}
__device__ __forceinline__ void mma16816(float& c0, float& c1, float& c2, float& c3,
                                         uint32_t a0, uint32_t a1, uint32_t a2, uint32_t a3,
                                         uint32_t b0, uint32_t b1) {
    asm volatile("mma.sync.aligned.m16n8k16.row.col.f32.bf16.bf16.f32 "
                 "{%0,%1,%2,%3}, {%4,%5,%6,%7}, {%8,%9}, {%0,%1,%2,%3};"
                 : "+f"(c0), "+f"(c1), "+f"(c2), "+f"(c3)
                 : "r"(a0), "r"(a1), "r"(a2), "r"(a3), "r"(b0), "r"(b1));
}
__device__ __forceinline__ uint32_t pack_bf2(float a, float b) {
    unsigned short l = __bfloat16_as_ushort(__float2bfloat16_rn(a));
    unsigned short h = __bfloat16_as_ushort(__float2bfloat16_rn(b));
    return ((uint32_t)h << 16) | l;
}

// CTA tile 128x128; warp tile 64x32 (2m x 4n warps)
// BK=64 per stage: rows of 64 bf16 = 128B + 16B pad = 144B; 3 stages
#define ROWB 144
#define ABYTES (128*ROWB)           // 18432
#define STAGEB (2*ABYTES)           // 36864
#define NSTAGE 3
#define GSMEM (NSTAGE*STAGEB)       // 110592

// EPI: 0 bias->Cf ; 1 bias+res->Cf ; 2 gelu->Cp pair ; 3 res->Cf ; 4 plain->Cp pair
template<int EPI>
__global__ void __launch_bounds__(256, 2) gemm_mma(
    const bf16* __restrict__ Ab, const bf16* __restrict__ Bb,
    const float* __restrict__ bias, const float* __restrict__ resid,
    float* __restrict__ Cf, bf16* __restrict__ Cp, int N, int K)
{
    extern __shared__ char smem[];
    uint32_t sb = smem_u32(smem);
    int tid = threadIdx.x;
    int w = tid >> 5, lane = tid & 31;
    int bm = blockIdx.y * 128, bn = blockIdx.x * 128;
    const int lda = 2*K, ldb = 2*K;
    int m0 = (w & 1) * 64;
    int n0 = (w >> 1) * 32;

    const int KP = K >> 6;          // 64-col stages per pass
    const int TC = 3 * KP;

    float acc[4][4][4];
#pragma unroll
    for (int i = 0; i < 4; ++i)
#pragma unroll
        for (int j = 0; j < 4; ++j)
#pragma unroll
            for (int q = 0; q < 4; ++q) acc[i][j][q] = 0.f;

    // strength-reduced cp.async addressing:
    // thread tid copies A rows r0+{0,32,64,96} and B rows r0+{0,32,64,96} at column c0
    int r0 = tid >> 3;
    int c8 = (tid & 7) * 8;                 // element column of this thread's 16B chunk
    const bf16* gA0 = Ab + (long)(bm + r0)*lda + c8;
    const bf16* gB0 = Bb + (long)(bn + r0)*ldb + c8;
    uint32_t sOff = (uint32_t)r0*ROWB + (uint32_t)(tid & 7)*16;

    auto issue = [&](int t) {
        int p = t / KP, kk = t - p*KP;
        int aoff = (p == 1 ? K : 0) + kk*64;
        int boff = (p == 2 ? K : 0) + kk*64;
        uint32_t base = sb + (t % NSTAGE)*STAGEB + sOff;
#pragma unroll
        for (int j = 0; j < 4; ++j)
            cp16(base + j*(32*ROWB), gA0 + aoff + (long)j*32*lda);
#pragma unroll
        for (int j = 0; j < 4; ++j)
            cp16(base + ABYTES + j*(32*ROWB), gB0 + boff + (long)j*32*ldb);
        asm volatile("cp.async.commit_group;" ::: "memory");
    };

    issue(0); issue(1);

    uint32_t aRow = (uint32_t)(m0 + (lane & 15)) * ROWB + ((lane >> 4) * 8) * 2;
    uint32_t bRow = (uint32_t)(n0 + (lane & 7) + ((lane >> 4) & 1) * 8) * ROWB
                    + (((lane >> 3) & 1) * 8) * 2;

    for (int t = 0; t < TC; ++t) {
        // per-thread wait for group t, THEN barrier => group t complete for all threads
        if (t + 1 < TC) {
            asm volatile("cp.async.wait_group 1;" ::: "memory");
        } else {
            asm volatile("cp.async.wait_group 0;" ::: "memory");
        }
        __syncthreads();
        // slot (t+2)%3 == slot (t-1)%3: its readers are all past the barrier above
        if (t + 2 < TC) issue(t + 2);
        uint32_t Asm = sb + (t % NSTAGE)*STAGEB;
        uint32_t Bsm = Asm + ABYTES;
#pragma unroll
        for (int k16 = 0; k16 < 4; ++k16) {
            uint32_t a[4][4], b[2][4];
#pragma unroll
            for (int mi = 0; mi < 4; ++mi)
                ldmx4(a[mi][0], a[mi][1], a[mi][2], a[mi][3],
                      Asm + aRow + mi*16*ROWB + k16*32);
#pragma unroll
            for (int bj = 0; bj < 2; ++bj)
                ldmx4(b[bj][0], b[bj][1], b[bj][2], b[bj][3],
                      Bsm + bRow + bj*16*ROWB + k16*32);
#pragma unroll
            for (int mi = 0; mi < 4; ++mi)
#pragma unroll
                for (int nj = 0; nj < 4; ++nj) {
                    uint32_t b0 = b[nj >> 1][(nj & 1) ? 2 : 0];
                    uint32_t b1 = b[nj >> 1][(nj & 1) ? 3 : 1];
                    mma16816(acc[mi][nj][0], acc[mi][nj][1], acc[mi][nj][2], acc[mi][nj][3],
                             a[mi][0], a[mi][1], a[mi][2], a[mi][3], b0, b1);
                }
        }
    }

    // epilogue
    int rbase = bm + m0 + (lane >> 2);
    int cbase = bn + n0 + (lane & 3) * 2;
#pragma unroll
    for (int mi = 0; mi < 4; ++mi) {
#pragma unroll
        for (int half = 0; half < 2; ++half) {
            long row = rbase + mi*16 + half*8;
#pragma unroll
            for (int nj = 0; nj < 4; ++nj) {
                int col = cbase + nj*8;
                float v0 = acc[mi][nj][half*2 + 0];
                float v1 = acc[mi][nj][half*2 + 1];
                if (EPI == 0 || EPI == 1) {
                    v0 += __ldg(bias + col);
                    v1 += __ldg(bias + col + 1);
                }
                if (EPI == 1 || EPI == 3) {
                    float2 rv = *(const float2*)(resid + row*N + col);
                    v0 += rv.x; v1 += rv.y;
                }
                if (EPI == 2 || EPI == 4) {
                    if (EPI == 2) {
                        v0 = 0.5f*v0*(1.f + erff(v0*0.70710678118654752f));
                        v1 = 0.5f*v1*(1.f + erff(v1*0.70710678118654752f));
                    }
                    bf16 h0 = __float2bfloat16_rn(v0), h1 = __float2bfloat16_rn(v1);
                    uint32_t hw = ((uint32_t)__bfloat16_as_ushort(h1) << 16) | __bfloat16_as_ushort(h0);
                    uint32_t lw = pack_bf2(v0 - __bfloat162float(h0), v1 - __bfloat162float(h1));
                    *(uint32_t*)(Cp + row*(2L*N) + col)     = hw;
                    *(uint32_t*)(Cp + row*(2L*N) + N + col) = lw;
                } else {
                    *(float2*)(Cf + row*N + col) = make_float2(v0, v1);
                }
            }
        }
    }
}

// ---------------- weight fp32 -> bf16 hi/lo pair (row-major) ----------------
__global__ void cvt_pair_w(const float* __restrict__ W, bf16* __restrict__ dst,
                           int K, int total)
{
    int i = blockIdx.x*256 + threadIdx.x;
    if (i >= total) return;
    int n = i / K, k = i - n*K;
    float v = W[i];
    bf16 h = __float2bfloat16_rn(v);
    float lo = v - __bfloat162float(h);
    dst[(long)n*2*K + k]     = h;
    dst[(long)n*2*K + K + k] = __float2bfloat16_rn(lo);
}

// ---------------- transposed pair conversion (z-batched): W[E][D] -> dst[d][2E] ----------------
__global__ void cvt_pair_wT2(const float* __restrict__ W0, bf16* __restrict__ D0,
                             const float* __restrict__ W1, bf16* __restrict__ D1)
{
    __shared__ float tile[32][33];
    const float* W = blockIdx.z ? W1 : W0;
    bf16* dst = blockIdx.z ? D1 : D0;
    int d0 = blockIdx.x*32, e0 = blockIdx.y*32;
    int lx = threadIdx.x, ly = threadIdx.y;   // 32 x 8
#pragma unroll
    for (int i = 0; i < 32; i += 8)
        tile[ly+i][lx] = W[(long)(e0+ly+i)*DMODEL + d0+lx];
    __syncthreads();
#pragma unroll
    for (int i = 0; i < 32; i += 8) {
        int d = d0 + ly + i, e = e0 + lx;
        float v = tile[lx][ly+i];
        bf16 h = __float2bfloat16_rn(v);
        dst[(long)d*1024 + e]       = h;
        dst[(long)d*1024 + 512 + e] = __float2bfloat16_rn(v - __bfloat162float(h));
    }
}

// ---------------- conv embedding ----------------
__global__ void __launch_bounds__(512) conv_embed(const float* __restrict__ x,
                                                  const float* __restrict__ w)
{
    __shared__ float xs[18][CIN];
    int b = blockIdx.x, l0 = blockIdx.y * 16;
    int tid = threadIdx.x;
    for (int i = tid; i < 18*CIN; i += 512) {
        int r = i / CIN, c = i % CIN;
        int l = (l0 - 1 + r + SEQL) & (SEQL-1);
        xs[r][c] = x[(b*SEQL + l)*CIN + c];
    }
    __syncthreads();
    int d = tid;
    float wr[63];
#pragma unroll
    for (int i = 0; i < 63; ++i) wr[i] = __ldg(w + d*63 + i);
    for (int ll = 0; ll < 16; ++ll) {
        float acc = 0.f;
#pragma unroll
        for (int c = 0; c < CIN; ++c) {
            acc = fmaf(xs[ll+0][c], wr[c*3+0], acc);
            acc = fmaf(xs[ll+1][c], wr[c*3+1], acc);
            acc = fmaf(xs[ll+2][c], wr[c*3+2], acc);
        }
        long row = (long)b*SEQL + l0 + ll;
        g_x[row*DMODEL + d] = acc;
        bf16 h = __float2bfloat16_rn(acc);
        g_cvA[row*1024 + d]       = h;
        g_cvA[row*1024 + 512 + d] = __float2bfloat16_rn(acc - __bfloat162float(h));
    }
}

// ---------------- transpose y,x: [B,L,D] -> [B,D,L] ----------------
__global__ void transpose_qk()
{
    __shared__ float tile[32][33];
    int z = blockIdx.z;
    int b = z >> 1;
    const float* src = (z & 1) ? g_x : g_q;     // k-role = x, q-role = y
    float* dst = (z & 1) ? g_kT : g_qT;
    int l0 = blockIdx.y * 32, d0 = blockIdx.x * 32;
    int lx = threadIdx.x, ly = threadIdx.y;
#pragma unroll
    for (int i = 0; i < 32; i += 8)
        tile[ly+i][lx] = src[((long)b*SEQL + l0+ly+i)*DMODEL + d0+lx];
    __syncthreads();
#pragma unroll
    for (int i = 0; i < 32; i += 8)
        dst[((long)b*DMODEL + d0+ly+i)*SEQL + l0+lx] = tile[lx][ly+i];
}

// ---------------- FFT ----------------
__device__ __forceinline__ int brev10(int x) { return (int)(__brev((unsigned)x) >> 22); }

__device__ __forceinline__ void fft1024(float* zr, float* zi,
                                        const float* wre, const float* wim, int tid)
{
#pragma unroll
    for (int s = 1; s <= 10; ++s) {
        int half = 1 << (s-1);
        int tshift = 10 - s;
        for (int bf = tid; bf < 512; bf += 256) {
            int grp = bf >> (s-1);
            int pos = bf & (half-1);
            int i = (grp << s) + pos;
            int j = i + half;
            float wr = wre[pos << tshift], wi = wim[pos << tshift];
            float xr = zr[j], xi = zi[j];
            float tr = wr*xr - wi*xi;
            float ti = wr*xi + wi*xr;
            float ur = zr[i], ui = zi[i];
            zr[i] = ur + tr; zi[i] = ui + ti;
            zr[j] = ur - tr; zi[j] = ui - ti;
        }
        __syncthreads();
    }
}

__global__ void __launch_bounds__(256) fft_corr()
{
    __shared__ float wre[512], wim[512];
    __shared__ float zr[1024], zi[1024];
    __shared__ float pr[1024], pi[1024];
    int tid = threadIdx.x;
    int chunk = blockIdx.x;
    int b = blockIdx.y;
    for (int j = tid; j < 512; j += 256) {
        float s, c;
        sincosf(-6.283185307179586476f * (float)j / 1024.f, &s, &c);
        wre[j] = c; wim[j] = s;
    }
    for (int f = tid; f < 1024; f += 256) { pr[f] = 0.f; pi[f] = 0.f; }
    __syncthreads();
    for (int ch = 0; ch < 16; ++ch) {
        int d = chunk*16 + ch;
        const float* qrow = g_qT + ((long)b*DMODEL + d)*SEQL;
        const float* krow = g_kT + ((long)b*DMODEL + d)*SEQL;
        for (int l = tid; l < 1024; l += 256) {
            int p = brev10(l);
            zr[p] = qrow[l];
            zi[p] = krow[l];
        }
        __syncthreads();
        fft1024(zr, zi, wre, wim, tid);
        for (int f = tid; f < 1024; f += 256) {
            int nf = (1024 - f) & 1023;
            float Zr = zr[f], Zi = zi[f];
            float Zcr = zr[nf], Zci = -zi[nf];
            float Qr = 0.5f*(Zr + Zcr), Qi = 0.5f*(Zi + Zci);
            float Mr = Zr - Zcr,       Mi = Zi - Zci;
            float Kr = 0.5f*Mi,        Ki = -0.5f*Mr;
            pr[f] += Qr*Kr + Qi*Ki;
            pi[f] += Qi*Kr - Qr*Ki;
        }
        __syncthreads();
    }
    float2* out = g_Spart + ((long)b*32 + chunk)*1024;
    for (int f = tid; f < 1024; f += 256) out[f] = make_float2(pr[f], pi[f]);
}

__global__ void reduce_S()
{
    int b = blockIdx.x;
    int f = blockIdx.y*256 + threadIdx.x;
    float sr = 0.f, si = 0.f;
    for (int c = 0; c < 32; ++c) {
        float2 v = g_Spart[((long)b*32 + c)*1024 + f];
        sr += v.x; si += v.y;
    }
    g_S[b*1024 + f] = make_float2(sr, si);
}

__global__ void __launch_bounds__(256) ifft_mv()
{
    __shared__ float wre[512], wim[512];
    __shared__ float zr[1024], zi[1024];
    int tid = threadIdx.x;
    int b = blockIdx.x;
    for (int j = tid; j < 512; j += 256) {
        float s, c;
        sincosf(-6.283185307179586476f * (float)j / 1024.f, &s, &c);
        wre[j] = c; wim[j] = s;
    }
    __syncthreads();
    for (int f = tid; f < 1024; f += 256) {
        int p = brev10(f);
        float2 v = g_S[b*1024 + f];
        zr[p] = v.x; zi[p] = -v.y;
    }
    __syncthreads();
    fft1024(zr, zi, wre, wim, tid);
    const float scale = 1.f / (1024.f * 512.f);
    for (int t = tid; t < 1024; t += 256)
        g_mv[b*1024 + t] = zr[t] * scale;
}

// ---------------- top-6 + softmax ----------------
__global__ void __launch_bounds__(256) topk_softmax()
{
    __shared__ float vals[1024];
    __shared__ float rv[256];
    __shared__ int   ri[256];
    __shared__ float topv[TOPK];
    __shared__ int   topi[TOPK];
    int b = blockIdx.x, tid = threadIdx.x;
    for (int i = tid; i < 1024; i += 256) vals[i] = g_mv[b*1024 + i];
    __syncthreads();
    for (int it = 0; it < TOPK; ++it) {
        float best = -3.0e38f; int bi = 0x7fffffff;
        for (int i = tid; i < 1024; i += 256) {
            float v = vals[i];
            if (v > best) { best = v; bi = i; }
        }
        rv[tid] = best; ri[tid] = bi;
        __syncthreads();
        for (int s = 128; s > 0; s >>= 1) {
            if (tid < s) {
                float v2 = rv[tid+s]; int i2 = ri[tid+s];
                if (v2 > rv[tid] || (v2 == rv[tid] && i2 < ri[tid])) { rv[tid] = v2; ri[tid] = i2; }
            }
            __syncthreads();
        }
        if (tid == 0) { topv[it] = rv[0]; topi[it] = ri[0]; vals[ri[0]] = -3.0e38f; }
        __syncthreads();
    }
    if (tid == 0) {
        float mx = topv[0], se = 0.f, e[TOPK];
        for (int i = 0; i < TOPK; ++i) { e[i] = expf(topv[i] - mx); se += e[i]; }
        for (int i = 0; i < TOPK; ++i) { g_w6[b*TOPK+i] = e[i]/se; g_d6[b*TOPK+i] = topi[i]; }
    }
}

// ---------------- aggregation of x (linear path) -> bf16 pair ----------------
__global__ void aggregate()
{
    int idx = blockIdx.x*256 + threadIdx.x;
    int d = idx & 511;
    int l = (idx >> 9) & 1023;
    int b = idx >> 19;
    const float* vb = g_x + ((long)b << 19);
    float acc = 0.f;
#pragma unroll
    for (int i = 0; i < TOPK; ++i) {
        int dl = __ldg(g_d6 + b*TOPK + i);
        float w = __ldg(g_w6 + b*TOPK + i);
        acc = fmaf(w, vb[(((l + dl) & 1023) << 9) + d], acc);
    }
    long row = (long)b*1024 + l;
    bf16 h = __float2bfloat16_rn(acc);
    g_cvA[row*1024 + d]       = h;
    g_cvA[row*1024 + 512 + d] = __float2bfloat16_rn(acc - __bfloat162float(h));
}

// ---------------- series decomp ----------------
__global__ void decomp()
{
    int t = blockIdx.x*256 + threadIdx.x;
    int d = t & 511;
    int r = t >> 9;
    int seg = r & 7;
    int b = r >> 3;
    const float* xb = g_tmp + ((long)b << 19);
    float* yb = g_x + ((long)b << 19);
    int l0 = seg << 7;
    float sum = 0.f;
#pragma unroll
    for (int j = -12; j <= 12; ++j) {
        int lj = l0 + j; lj = lj < 0 ? 0 : (lj > 1023 ? 1023 : lj);
        sum += xb[(lj << 9) + d];
    }
    for (int l = l0; l < l0 + 128; ++l) {
        float xv = xb[(l << 9) + d];
        float y = xv - sum * (1.f/25.f);
        yb[(l << 9) + d] = y;
        long row = (long)b*1024 + l;
        bf16 h = __float2bfloat16_rn(y);
        g_cvA[row*1024 + d]       = h;
        g_cvA[row*1024 + 512 + d] = __float2bfloat16_rn(y - __bfloat162float(h));
        int la = l + 13; la = la > 1023 ? 1023 : la;
        int lr = l - 12; lr = lr < 0 ? 0 : lr;
        sum += xb[(la << 9) + d] - xb[(lr << 9) + d];
    }
}

// ---------------- special layernorm ----------------
__global__ void __launch_bounds__(256) ln_rows(const float* __restrict__ gam,
                                               const float* __restrict__ bet)
{
    int row = blockIdx.x;
    const float* xr = g_x + (long)row*512;
    int tid = threadIdx.x;
    float v0 = xr[tid], v1 = xr[tid+256];
    float s = v0 + v1, s2 = v0*v0 + v1*v1;
#pragma unroll
    for (int o = 16; o; o >>= 1) {
        s  += __shfl_down_sync(0xffffffffu, s,  o);
        s2 += __shfl_down_sync(0xffffffffu, s2, o);
    }
    __shared__ float sh1[8], sh2[8];
    __shared__ float mu_s, rs_s;
    int wid = tid >> 5, ln = tid & 31;
    if (!ln) { sh1[wid] = s; sh2[wid] = s2; }
    __syncthreads();
    if (tid == 0) {
        float S = 0.f, S2 = 0.f;
        for (int i = 0; i < 8; ++i) { S += sh1[i]; S2 += sh2[i]; }
        float mu = S * (1.f/512.f);
        float var = S2 * (1.f/512.f) - mu*mu;
        mu_s = mu; rs_s = rsqrtf(var + 1e-5f);
    }
    __syncthreads();
    float mu = mu_s, rs = rs_s;
    g_q[(long)row*512 + tid]       = (v0 - mu)*rs*gam[tid]     + bet[tid];
    g_q[(long)row*512 + tid + 256] = (v1 - mu)*rs*gam[tid+256] + bet[tid+256];
}

__global__ void colmean_k()
{
    int t = blockIdx.x*256 + threadIdx.x;
    int b = t >> 9, d = t & 511;
    const float* p = g_q + ((long)b << 19) + d;
    float s = 0.f;
    for (int l = 0; l < 1024; ++l) s += p[l << 9];
    g_colmean[t] = s * (1.f/1024.f);
}

__global__ void gelu_mask(const float* __restrict__ mark)
{
    int i = blockIdx.x*256 + threadIdx.x;
    int d = i & 511;
    int r = i >> 9;
    int b = r >> 10;
    float v = g_q[i] - g_colmean[(b << 9) + d];
    float g = 0.5f*v*(1.f + erff(v*0.70710678118654752f));
    g_k[i] = g * mark[r];
}

// ---------------- final projection ----------------
__global__ void __launch_bounds__(256) proj_partial(const float* __restrict__ Wp)
{
    int ks = blockIdx.x;
    int tid = threadIdx.x;
    const int CH = LD/64;
    int wid = tid >> 5, ln = tid & 31;
    for (int n = 0; n < NCLS; ++n) {
        const float* wrow = Wp + (long)n*LD + (long)ks*CH;
        float acc[32];
#pragma unroll
        for (int b2 = 0; b2 < 32; ++b2) acc[b2] = 0.f;
        for (int k = tid; k < CH; k += 256) {
            float wv = wrow[k];
            long base = (long)ks*CH + k;
#pragma unroll
            for (int b2 = 0; b2 < 32; ++b2)
                acc[b2] = fmaf(wv, g_k[((long)b2 << 19) + base], acc[b2]);
        }
#pragma unroll
        for (int b2 = 0; b2 < 32; ++b2) {
            float v = acc[b2];
#pragma unroll
            for (int o = 16; o; o >>= 1) v += __shfl_down_sync(0xffffffffu, v, o);
            if (!ln) g_part[(((long)ks*NCLS + n)*8 + wid)*32 + b2] = v;
        }
    }
}

__global__ void proj_final(const float* __restrict__ bp, float* __restrict__ out)
{
    int t = threadIdx.x;
    if (t >= 32*NCLS) return;
    int b = t / NCLS, n = t % NCLS;
    float s = bp[n];
    for (int ks = 0; ks < 64; ++ks)
        for (int w = 0; w < 8; ++w)
            s += g_part[(((long)ks*NCLS + n)*8 + w)*32 + b];
    out[b*NCLS + n] = s;
}

// ---------------- host ----------------
extern "C" void kernel_launch(void* const* d_in, const int* in_sizes, int n_in,
                              void* d_out, int out_size)
{
    const float* x_enc   = (const float*)d_in[0];
    const float* x_mark  = (const float*)d_in[1];
    const float* conv_w  = (const float*)d_in[2];
    const float* Wq      = (const float*)d_in[3];
    const float* bq      = (const float*)d_in[4];
    const float* Wk      = (const float*)d_in[5];
    const float* Wv      = (const float*)d_in[7];
    const float* Wo      = (const float*)d_in[9];
    const float* bo      = (const float*)d_in[10];
    const float* Wff1    = (const float*)d_in[11];
    const float* Wff2    = (const float*)d_in[12];
    const float* ln_g    = (const float*)d_in[13];
    const float* ln_b    = (const float*)d_in[14];
    const float* Wproj   = (const float*)d_in[15];
    const float* bproj   = (const float*)d_in[16];
    float* out = (float*)d_out;

    float *px, *pq, *ptmp;
    bf16 *pcvA, *pcvB, *pcvH;
    cudaGetSymbolAddress((void**)&px,   g_x);
    cudaGetSymbolAddress((void**)&pq,   g_q);
    cudaGetSymbolAddress((void**)&ptmp, g_tmp);
    cudaGetSymbolAddress((void**)&pcvA, g_cvA);
    cudaGetSymbolAddress((void**)&pcvB, g_cvB);
    cudaGetSymbolAddress((void**)&pcvH, g_cvH);

    // g_cvB sub-allocation (bf16 elements, total 4M)
    bf16* wqT_p = pcvB;
    bf16* wkT_p = pcvB + (size_t)512*1024;
    bf16* wvT_p = pcvB + (size_t)1024*1024;
    bf16* wo_p  = pcvB + (size_t)1536*1024;
    bf16* P_p   = pcvB + (size_t)2048*1024;
    bf16* NN_p  = pcvB + (size_t)2560*1024;
    bf16* w1_p  = pcvB;                          // reuse after a-GEMM
    bf16* w2_p  = pcvB + (size_t)2048*1024;      // reuse after a-GEMM

    cudaFuncSetAttribute(gemm_mma<0>, cudaFuncAttributeMaxDynamicSharedMemorySize, GSMEM);
    cudaFuncSetAttribute(gemm_mma<1>, cudaFuncAttributeMaxDynamicSharedMemorySize, GSMEM);
    cudaFuncSetAttribute(gemm_mma<2>, cudaFuncAttributeMaxDynamicSharedMemorySize, GSMEM);
    cudaFuncSetAttribute(gemm_mma<3>, cudaFuncAttributeMaxDynamicSharedMemorySize, GSMEM);
    cudaFuncSetAttribute(gemm_mma<4>, cudaFuncAttributeMaxDynamicSharedMemorySize, GSMEM);

    conv_embed<<<dim3(BATCH, SEQL/16), 512>>>(x_enc, conv_w);

    for (int l = 0; l < NLAYERS; ++l) {
        const float* wq = Wq + (long)l*DMODEL*DMODEL;
        const float* wk = Wk + (long)l*DMODEL*DMODEL;
        const float* wv = Wv + (long)l*DMODEL*DMODEL;
        const float* wo = Wo + (long)l*DMODEL*DMODEL;
        const float* w1 = Wff1 + (long)l*DFF*DMODEL;
        const float* w2 = Wff2 + (long)l*DMODEL*DFF;

        // Wq^T, Wk^T pairs in one launch; then P = (Wk^T Wq) pair
        cvt_pair_wT2<<<dim3(16,16,2), dim3(32,8)>>>(wq, wqT_p, wk, wkT_p);
        gemm_mma<4><<<dim3(4,4), 256, GSMEM>>>(wkT_p, wqT_p, nullptr, nullptr, nullptr, P_p, DMODEL, DMODEL);

        // y = x @ P^T  (corr surrogate; bq zeros)
        gemm_mma<0><<<dim3(DMODEL/128, BL/128), 256, GSMEM>>>(pcvA, P_p, bq + l*DMODEL, nullptr, pq, nullptr, DMODEL, DMODEL);

        // Wv^T pair + Wo pair; NN = Wo·Wv pair
        cvt_pair_wT2<<<dim3(16,16,1), dim3(32,8)>>>(wv, wvT_p, wv, wvT_p);
        cvt_pair_w<<<(DMODEL*DMODEL+255)/256, 256>>>(wo, wo_p, DMODEL, DMODEL*DMODEL);
        gemm_mma<4><<<dim3(4,4), 256, GSMEM>>>(wo_p, wvT_p, nullptr, nullptr, nullptr, NN_p, DMODEL, DMODEL);

        // autocorrelation: S = sum_d Yf * conj(Xf)
        transpose_qk<<<dim3(DMODEL/32, SEQL/32, BATCH*2), dim3(32, 8)>>>();
        fft_corr<<<dim3(32, BATCH), 256>>>();
        reduce_S<<<dim3(BATCH, 4), 256>>>();
        ifft_mv<<<BATCH, 256>>>();
        topk_softmax<<<BATCH, 256>>>();
        aggregate<<<(BL*DMODEL)/256, 256>>>();     // xs pair -> g_cvA

        // a = xs @ NN^T + bo + x -> g_tmp ; then decomp
        gemm_mma<1><<<dim3(DMODEL/128, BL/128), 256, GSMEM>>>(pcvA, NN_p, bo + l*DMODEL, px, ptmp, nullptr, DMODEL, DMODEL);
        decomp<<<(BATCH*DMODEL*8)/256, 256>>>();

        // FFN
        cvt_pair_w<<<(DFF*DMODEL+255)/256, 256>>>(w1, w1_p, DMODEL, DFF*DMODEL);
        gemm_mma<2><<<dim3(DFF/128, BL/128), 256, GSMEM>>>(pcvA, w1_p, nullptr, nullptr, nullptr, pcvH, DFF, DMODEL);
        cvt_pair_w<<<(DMODEL*DFF+255)/256, 256>>>(w2, w2_p, DFF, DMODEL*DFF);
        gemm_mma<3><<<dim3(DMODEL/128, BL/128), 256, GSMEM>>>(pcvH, w2_p, nullptr, px, ptmp, nullptr, DMODEL, DFF);
        decomp<<<(BATCH*DMODEL*8)/256, 256>>>();
    }

    ln_rows<<<BL, 256>>>(ln_g, ln_b);
    colmean_k<<<(BATCH*DMODEL)/256, 256>>>();
    gelu_mask<<<(BL*DMODEL)/256, 256>>>(x_mark);
    proj_partial<<<64, 256>>>(Wproj);
    proj_final<<<1, 512>>>(bproj, out);
}

// round 17
// speedup vs baseline: 1.0274x; 1.0274x over previous
#include <cuda_runtime.h>
#include <cuda_bf16.h>
#include <cstdint>
#include <stdint.h>
#include <math.h>

#define BATCH 32
#define SEQL 1024
#define CIN 21
#define DMODEL 512
#define DFF 2048
#define NLAYERS 3
#define TOPK 6
#define NCLS 10
#define BL (BATCH*SEQL)        // 32768
#define LD (SEQL*DMODEL)       // 524288
#define PSPLIT 128

typedef __nv_bfloat16 bf16;

// ---------------- scratch ----------------
__device__ float g_x[BL*DMODEL];
__device__ float g_q[BL*DMODEL];               // y (corr path) / LN output later
__device__ float g_k[BL*DMODEL];               // final gelu-masked output
__device__ float g_qT[BL*DMODEL];
__device__ float g_kT[BL*DMODEL];
__device__ float g_tmp[BL*DMODEL];
__device__ bf16  g_cvA[(size_t)BL*1024];        // act pair [M][hi 512 | lo 512]
__device__ bf16  g_cvH[(size_t)BL*4096];        // FFN1 out pair [M][hi 2048 | lo 2048]
__device__ bf16  g_cvB[(size_t)2048*2048];      // weight pairs (sub-allocated)
__device__ float2 g_Spart[BATCH*32*SEQL];
__device__ float2 g_S[BATCH*SEQL];
__device__ float g_mv[BATCH*SEQL];
__device__ float g_w6[BATCH*TOPK];
__device__ int   g_d6[BATCH*TOPK];
__device__ float g_colmean[BATCH*DMODEL];
__device__ float g_part[PSPLIT*NCLS*8*BATCH];

// ---------------- helpers ----------------
__device__ __forceinline__ uint32_t smem_u32(const void* p) {
    uint32_t a;
    asm("{ .reg .u64 t; cvta.to.shared.u64 t, %1; cvt.u32.u64 %0, t; }" : "=r"(a) : "l"(p));
    return a;
}
__device__ __forceinline__ void cp16(uint32_t s, const void* g) {
    asm volatile("cp.async.cg.shared.global [%0], [%1], 16;" :: "r"(s), "l"(g));
}
__device__ __forceinline__ void ldmx4(uint32_t& r0, uint32_t& r1, uint32_t& r2, uint32_t& r3, uint32_t a) {
    asm volatile("ldmatrix.sync.aligned.m8n8.x4.shared.b16 {%0,%1,%2,%3}, [%4];"
                 : "=r"(r0), "=r"(r1), "=r"(r2), "=r"(r3) : "r"(a));
}
__device__ __forceinline__ void mma16816(float& c0, float& c1, float& c2, float& c3,
                                         uint32_t a0, uint32_t a1, uint32_t a2, uint32_t a3,
                                         uint32_t b0, uint32_t b1) {
    asm volatile("mma.sync.aligned.m16n8k16.row.col.f32.bf16.bf16.f32 "
                 "{%0,%1,%2,%3}, {%4,%5,%6,%7}, {%8,%9}, {%0,%1,%2,%3};"
                 : "+f"(c0), "+f"(c1), "+f"(c2), "+f"(c3)
                 : "r"(a0), "r"(a1), "r"(a2), "r"(a3), "r"(b0), "r"(b1));
}
__device__ __forceinline__ uint32_t pack_bf2(float a, float b) {
    unsigned short l = __bfloat16_as_ushort(__float2bfloat16_rn(a));
    unsigned short h = __bfloat16_as_ushort(__float2bfloat16_rn(b));
    return ((uint32_t)h << 16) | l;
}

// CTA tile 128x128; warp tile 64x32 (2m x 4n warps)
// BK=64 per stage: rows of 64 bf16 = 128B + 16B pad = 144B; 3 stages
#define ROWB 144
#define ABYTES (128*ROWB)           // 18432
#define STAGEB (2*ABYTES)           // 36864
#define NSTAGE 3
#define GSMEM (NSTAGE*STAGEB)       // 110592

// shared GEMM body. EPI: 0 bias->Cf ; 1 bias+res->Cf ; 2 gelu->Cp pair ; 3 res->Cf ; 4 plain->Cp pair
template<int EPI>
__device__ __forceinline__ void gemm_body(
    const bf16* __restrict__ Ab, const bf16* __restrict__ Bb,
    const float* __restrict__ bias, const float* __restrict__ resid,
    float* __restrict__ Cf, bf16* __restrict__ Cp, int N, int K,
    int bm, int bn, char* smem)
{
    uint32_t sb = smem_u32(smem);
    int tid = threadIdx.x;
    int w = tid >> 5, lane = tid & 31;
    const int lda = 2*K, ldb = 2*K;
    int m0 = (w & 1) * 64;
    int n0 = (w >> 1) * 32;

    const int KP = K >> 6;
    const int TC = 3 * KP;

    float acc[4][4][4];
#pragma unroll
    for (int i = 0; i < 4; ++i)
#pragma unroll
        for (int j = 0; j < 4; ++j)
#pragma unroll
            for (int q = 0; q < 4; ++q) acc[i][j][q] = 0.f;

    int r0 = tid >> 3;
    int c8 = (tid & 7) * 8;
    const bf16* gA0 = Ab + (long)(bm + r0)*lda + c8;
    const bf16* gB0 = Bb + (long)(bn + r0)*ldb + c8;
    uint32_t sOff = (uint32_t)r0*ROWB + (uint32_t)(tid & 7)*16;

    auto issue = [&](int t) {
        int p = t / KP, kk = t - p*KP;
        int aoff = (p == 1 ? K : 0) + kk*64;
        int boff = (p == 2 ? K : 0) + kk*64;
        uint32_t base = sb + (t % NSTAGE)*STAGEB + sOff;
#pragma unroll
        for (int j = 0; j < 4; ++j)
            cp16(base + j*(32*ROWB), gA0 + aoff + (long)j*32*lda);
#pragma unroll
        for (int j = 0; j < 4; ++j)
            cp16(base + ABYTES + j*(32*ROWB), gB0 + boff + (long)j*32*ldb);
        asm volatile("cp.async.commit_group;" ::: "memory");
    };

    issue(0); issue(1);

    uint32_t aRow = (uint32_t)(m0 + (lane & 15)) * ROWB + ((lane >> 4) * 8) * 2;
    uint32_t bRow = (uint32_t)(n0 + (lane & 7) + ((lane >> 4) & 1) * 8) * ROWB
                    + (((lane >> 3) & 1) * 8) * 2;

    for (int t = 0; t < TC; ++t) {
        if (t + 1 < TC) {
            asm volatile("cp.async.wait_group 1;" ::: "memory");
        } else {
            asm volatile("cp.async.wait_group 0;" ::: "memory");
        }
        __syncthreads();
        if (t + 2 < TC) issue(t + 2);
        uint32_t Asm = sb + (t % NSTAGE)*STAGEB;
        uint32_t Bsm = Asm + ABYTES;
#pragma unroll
        for (int k16 = 0; k16 < 4; ++k16) {
            uint32_t a[4][4], b[2][4];
#pragma unroll
            for (int mi = 0; mi < 4; ++mi)
                ldmx4(a[mi][0], a[mi][1], a[mi][2], a[mi][3],
                      Asm + aRow + mi*16*ROWB + k16*32);
#pragma unroll
            for (int bj = 0; bj < 2; ++bj)
                ldmx4(b[bj][0], b[bj][1], b[bj][2], b[bj][3],
                      Bsm + bRow + bj*16*ROWB + k16*32);
#pragma unroll
            for (int mi = 0; mi < 4; ++mi)
#pragma unroll
                for (int nj = 0; nj < 4; ++nj) {
                    uint32_t b0 = b[nj >> 1][(nj & 1) ? 2 : 0];
                    uint32_t b1 = b[nj >> 1][(nj & 1) ? 3 : 1];
                    mma16816(acc[mi][nj][0], acc[mi][nj][1], acc[mi][nj][2], acc[mi][nj][3],
                             a[mi][0], a[mi][1], a[mi][2], a[mi][3], b0, b1);
                }
        }
    }

    int rbase = bm + m0 + (lane >> 2);
    int cbase = bn + n0 + (lane & 3) * 2;
#pragma unroll
    for (int mi = 0; mi < 4; ++mi) {
#pragma unroll
        for (int half = 0; half < 2; ++half) {
            long row = rbase + mi*16 + half*8;
#pragma unroll
            for (int nj = 0; nj < 4; ++nj) {
                int col = cbase + nj*8;
                float v0 = acc[mi][nj][half*2 + 0];
                float v1 = acc[mi][nj][half*2 + 1];
                if (EPI == 0 || EPI == 1) {
                    v0 += __ldg(bias + col);
                    v1 += __ldg(bias + col + 1);
                }
                if (EPI == 1 || EPI == 3) {
                    float2 rv = *(const float2*)(resid + row*N + col);
                    v0 += rv.x; v1 += rv.y;
                }
                if (EPI == 2 || EPI == 4) {
                    if (EPI == 2) {
                        v0 = 0.5f*v0*(1.f + erff(v0*0.70710678118654752f));
                        v1 = 0.5f*v1*(1.f + erff(v1*0.70710678118654752f));
                    }
                    bf16 h0 = __float2bfloat16_rn(v0), h1 = __float2bfloat16_rn(v1);
                    uint32_t hw = ((uint32_t)__bfloat16_as_ushort(h1) << 16) | __bfloat16_as_ushort(h0);
                    uint32_t lw = pack_bf2(v0 - __bfloat162float(h0), v1 - __bfloat162float(h1));
                    *(uint32_t*)(Cp + row*(2L*N) + col)     = hw;
                    *(uint32_t*)(Cp + row*(2L*N) + N + col) = lw;
                } else {
                    *(float2*)(Cf + row*N + col) = make_float2(v0, v1);
                }
            }
        }
    }
}

template<int EPI>
__global__ void __launch_bounds__(256, 2) gemm_mma(
    const bf16* __restrict__ Ab, const bf16* __restrict__ Bb,
    const float* __restrict__ bias, const float* __restrict__ resid,
    float* __restrict__ Cf, bf16* __restrict__ Cp, int N, int K)
{
    extern __shared__ char smem[];
    gemm_body<EPI>(Ab, Bb, bias, resid, Cf, Cp, N, K,
                   blockIdx.y * 128, blockIdx.x * 128, smem);
}

// two small 512^3 pair-output GEMMs in one launch (z selects operands)
__global__ void __launch_bounds__(256, 2) gemm_small2(
    const bf16* __restrict__ A0, const bf16* __restrict__ B0, bf16* __restrict__ C0,
    const bf16* __restrict__ A1, const bf16* __restrict__ B1, bf16* __restrict__ C1)
{
    extern __shared__ char smem[];
    const bf16* Ab = blockIdx.z ? A1 : A0;
    const bf16* Bb = blockIdx.z ? B1 : B0;
    bf16* Cp = blockIdx.z ? C1 : C0;
    gemm_body<4>(Ab, Bb, nullptr, nullptr, nullptr, Cp, DMODEL, DMODEL,
                 blockIdx.y * 128, blockIdx.x * 128, smem);
}

// ---------------- weight fp32 -> bf16 hi/lo pair (row-major) ----------------
__global__ void cvt_pair_w(const float* __restrict__ W, bf16* __restrict__ dst,
                           int K, int total)
{
    int i = blockIdx.x*256 + threadIdx.x;
    if (i >= total) return;
    int n = i / K, k = i - n*K;
    float v = W[i];
    bf16 h = __float2bfloat16_rn(v);
    float lo = v - __bfloat162float(h);
    dst[(long)n*2*K + k]     = h;
    dst[(long)n*2*K + K + k] = __float2bfloat16_rn(lo);
}

// ---------------- layer weight prep: z=0..2 transposed pairs (Wq,Wk,Wv), z=3 row pair (Wo)
__global__ void wprep4(const float* __restrict__ Wq, bf16* __restrict__ Dq,
                       const float* __restrict__ Wk, bf16* __restrict__ Dk,
                       const float* __restrict__ Wv, bf16* __restrict__ Dv,
                       const float* __restrict__ Wo, bf16* __restrict__ Do)
{
    __shared__ float tile[32][33];
    int z = blockIdx.z;
    const float* W = (z == 0) ? Wq : (z == 1) ? Wk : (z == 2) ? Wv : Wo;
    bf16* dst = (z == 0) ? Dq : (z == 1) ? Dk : (z == 2) ? Dv : Do;
    int d0 = blockIdx.x*32, e0 = blockIdx.y*32;
    int lx = threadIdx.x, ly = threadIdx.y;   // 32 x 8
    if (z < 3) {
#pragma unroll
        for (int i = 0; i < 32; i += 8)
            tile[ly+i][lx] = W[(long)(e0+ly+i)*DMODEL + d0+lx];
        __syncthreads();
#pragma unroll
        for (int i = 0; i < 32; i += 8) {
            int d = d0 + ly + i, e = e0 + lx;
            float v = tile[lx][ly+i];
            bf16 h = __float2bfloat16_rn(v);
            dst[(long)d*1024 + e]       = h;
            dst[(long)d*1024 + 512 + e] = __float2bfloat16_rn(v - __bfloat162float(h));
        }
    } else {
#pragma unroll
        for (int i = 0; i < 32; i += 8) {
            int n = e0 + ly + i, k = d0 + lx;
            float v = W[(long)n*DMODEL + k];
            bf16 h = __float2bfloat16_rn(v);
            dst[(long)n*1024 + k]       = h;
            dst[(long)n*1024 + 512 + k] = __float2bfloat16_rn(v - __bfloat162float(h));
        }
    }
}

// ---------------- conv embedding ----------------
__global__ void __launch_bounds__(512) conv_embed(const float* __restrict__ x,
                                                  const float* __restrict__ w)
{
    __shared__ float xs[18][CIN];
    int b = blockIdx.x, l0 = blockIdx.y * 16;
    int tid = threadIdx.x;
    for (int i = tid; i < 18*CIN; i += 512) {
        int r = i / CIN, c = i % CIN;
        int l = (l0 - 1 + r + SEQL) & (SEQL-1);
        xs[r][c] = x[(b*SEQL + l)*CIN + c];
    }
    __syncthreads();
    int d = tid;
    float wr[63];
#pragma unroll
    for (int i = 0; i < 63; ++i) wr[i] = __ldg(w + d*63 + i);
    for (int ll = 0; ll < 16; ++ll) {
        float acc = 0.f;
#pragma unroll
        for (int c = 0; c < CIN; ++c) {
            acc = fmaf(xs[ll+0][c], wr[c*3+0], acc);
            acc = fmaf(xs[ll+1][c], wr[c*3+1], acc);
            acc = fmaf(xs[ll+2][c], wr[c*3+2], acc);
        }
        long row = (long)b*SEQL + l0 + ll;
        g_x[row*DMODEL + d] = acc;
        bf16 h = __float2bfloat16_rn(acc);
        g_cvA[row*1024 + d]       = h;
        g_cvA[row*1024 + 512 + d] = __float2bfloat16_rn(acc - __bfloat162float(h));
    }
}

// ---------------- transpose y,x: [B,L,D] -> [B,D,L] ----------------
__global__ void transpose_qk()
{
    __shared__ float tile[32][33];
    int z = blockIdx.z;
    int b = z >> 1;
    const float* src = (z & 1) ? g_x : g_q;
    float* dst = (z & 1) ? g_kT : g_qT;
    int l0 = blockIdx.y * 32, d0 = blockIdx.x * 32;
    int lx = threadIdx.x, ly = threadIdx.y;
#pragma unroll
    for (int i = 0; i < 32; i += 8)
        tile[ly+i][lx] = src[((long)b*SEQL + l0+ly+i)*DMODEL + d0+lx];
    __syncthreads();
#pragma unroll
    for (int i = 0; i < 32; i += 8)
        dst[((long)b*DMODEL + d0+ly+i)*SEQL + l0+lx] = tile[lx][ly+i];
}

// ---------------- FFT ----------------
__device__ __forceinline__ int brev10(int x) { return (int)(__brev((unsigned)x) >> 22); }

__device__ __forceinline__ void fft1024(float* zr, float* zi,
                                        const float* wre, const float* wim, int tid)
{
#pragma unroll
    for (int s = 1; s <= 10; ++s) {
        int half = 1 << (s-1);
        int tshift = 10 - s;
        for (int bf = tid; bf < 512; bf += 256) {
            int grp = bf >> (s-1);
            int pos = bf & (half-1);
            int i = (grp << s) + pos;
            int j = i + half;
            float wr = wre[pos << tshift], wi = wim[pos << tshift];
            float xr = zr[j], xi = zi[j];
            float tr = wr*xr - wi*xi;
            float ti = wr*xi + wi*xr;
            float ur = zr[i], ui = zi[i];
            zr[i] = ur + tr; zi[i] = ui + ti;
            zr[j] = ur - tr; zi[j] = ui - ti;
        }
        __syncthreads();
    }
}

__global__ void __launch_bounds__(256) fft_corr()
{
    __shared__ float wre[512], wim[512];
    __shared__ float zr[1024], zi[1024];
    __shared__ float pr[1024], pi[1024];
    int tid = threadIdx.x;
    int chunk = blockIdx.x;
    int b = blockIdx.y;
    for (int j = tid; j < 512; j += 256) {
        float s, c;
        sincosf(-6.283185307179586476f * (float)j / 1024.f, &s, &c);
        wre[j] = c; wim[j] = s;
    }
    for (int f = tid; f < 1024; f += 256) { pr[f] = 0.f; pi[f] = 0.f; }
    __syncthreads();
    for (int ch = 0; ch < 16; ++ch) {
        int d = chunk*16 + ch;
        const float* qrow = g_qT + ((long)b*DMODEL + d)*SEQL;
        const float* krow = g_kT + ((long)b*DMODEL + d)*SEQL;
        for (int l = tid; l < 1024; l += 256) {
            int p = brev10(l);
            zr[p] = qrow[l];
            zi[p] = krow[l];
        }
        __syncthreads();
        fft1024(zr, zi, wre, wim, tid);
        for (int f = tid; f < 1024; f += 256) {
            int nf = (1024 - f) & 1023;
            float Zr = zr[f], Zi = zi[f];
            float Zcr = zr[nf], Zci = -zi[nf];
            float Qr = 0.5f*(Zr + Zcr), Qi = 0.5f*(Zi + Zci);
            float Mr = Zr - Zcr,       Mi = Zi - Zci;
            float Kr = 0.5f*Mi,        Ki = -0.5f*Mr;
            pr[f] += Qr*Kr + Qi*Ki;
            pi[f] += Qi*Kr - Qr*Ki;
        }
        __syncthreads();
    }
    float2* out = g_Spart + ((long)b*32 + chunk)*1024;
    for (int f = tid; f < 1024; f += 256) out[f] = make_float2(pr[f], pi[f]);
}

__global__ void reduce_S()
{
    int b = blockIdx.x;
    int f = blockIdx.y*256 + threadIdx.x;
    float sr = 0.f, si = 0.f;
    for (int c = 0; c < 32; ++c) {
        float2 v = g_Spart[((long)b*32 + c)*1024 + f];
        sr += v.x; si += v.y;
    }
    g_S[b*1024 + f] = make_float2(sr, si);
}

__global__ void __launch_bounds__(256) ifft_mv()
{
    __shared__ float wre[512], wim[512];
    __shared__ float zr[1024], zi[1024];
    int tid = threadIdx.x;
    int b = blockIdx.x;
    for (int j = tid; j < 512; j += 256) {
        float s, c;
        sincosf(-6.283185307179586476f * (float)j / 1024.f, &s, &c);
        wre[j] = c; wim[j] = s;
    }
    __syncthreads();
    for (int f = tid; f < 1024; f += 256) {
        int p = brev10(f);
        float2 v = g_S[b*1024 + f];
        zr[p] = v.x; zi[p] = -v.y;
    }
    __syncthreads();
    fft1024(zr, zi, wre, wim, tid);
    const float scale = 1.f / (1024.f * 512.f);
    for (int t = tid; t < 1024; t += 256)
        g_mv[b*1024 + t] = zr[t] * scale;
}

// ---------------- top-6 + softmax ----------------
__global__ void __launch_bounds__(256) topk_softmax()
{
    __shared__ float vals[1024];
    __shared__ float rv[256];
    __shared__ int   ri[256];
    __shared__ float topv[TOPK];
    __shared__ int   topi[TOPK];
    int b = blockIdx.x, tid = threadIdx.x;
    for (int i = tid; i < 1024; i += 256) vals[i] = g_mv[b*1024 + i];
    __syncthreads();
    for (int it = 0; it < TOPK; ++it) {
        float best = -3.0e38f; int bi = 0x7fffffff;
        for (int i = tid; i < 1024; i += 256) {
            float v = vals[i];
            if (v > best) { best = v; bi = i; }
        }
        rv[tid] = best; ri[tid] = bi;
        __syncthreads();
        for (int s = 128; s > 0; s >>= 1) {
            if (tid < s) {
                float v2 = rv[tid+s]; int i2 = ri[tid+s];
                if (v2 > rv[tid] || (v2 == rv[tid] && i2 < ri[tid])) { rv[tid] = v2; ri[tid] = i2; }
            }
            __syncthreads();
        }
        if (tid == 0) { topv[it] = rv[0]; topi[it] = ri[0]; vals[ri[0]] = -3.0e38f; }
        __syncthreads();
    }
    if (tid == 0) {
        float mx = topv[0], se = 0.f, e[TOPK];
        for (int i = 0; i < TOPK; ++i) { e[i] = expf(topv[i] - mx); se += e[i]; }
        for (int i = 0; i < TOPK; ++i) { g_w6[b*TOPK+i] = e[i]/se; g_d6[b*TOPK+i] = topi[i]; }
    }
}

// ---------------- aggregation of x (linear path) -> bf16 pair ----------------
__global__ void aggregate()
{
    int idx = blockIdx.x*256 + threadIdx.x;
    int d = idx & 511;
    int l = (idx >> 9) & 1023;
    int b = idx >> 19;
    const float* vb = g_x + ((long)b << 19);
    float acc = 0.f;
#pragma unroll
    for (int i = 0; i < TOPK; ++i) {
        int dl = __ldg(g_d6 + b*TOPK + i);
        float w = __ldg(g_w6 + b*TOPK + i);
        acc = fmaf(w, vb[(((l + dl) & 1023) << 9) + d], acc);
    }
    long row = (long)b*1024 + l;
    bf16 h = __float2bfloat16_rn(acc);
    g_cvA[row*1024 + d]       = h;
    g_cvA[row*1024 + 512 + d] = __float2bfloat16_rn(acc - __bfloat162float(h));
}

// ---------------- series decomp ----------------
__global__ void decomp()
{
    int t = blockIdx.x*256 + threadIdx.x;
    int d = t & 511;
    int r = t >> 9;
    int seg = r & 7;
    int b = r >> 3;
    const float* xb = g_tmp + ((long)b << 19);
    float* yb = g_x + ((long)b << 19);
    int l0 = seg << 7;
    float sum = 0.f;
#pragma unroll
    for (int j = -12; j <= 12; ++j) {
        int lj = l0 + j; lj = lj < 0 ? 0 : (lj > 1023 ? 1023 : lj);
        sum += xb[(lj << 9) + d];
    }
    for (int l = l0; l < l0 + 128; ++l) {
        float xv = xb[(l << 9) + d];
        float y = xv - sum * (1.f/25.f);
        yb[(l << 9) + d] = y;
        long row = (long)b*1024 + l;
        bf16 h = __float2bfloat16_rn(y);
        g_cvA[row*1024 + d]       = h;
        g_cvA[row*1024 + 512 + d] = __float2bfloat16_rn(y - __bfloat162float(h));
        int la = l + 13; la = la > 1023 ? 1023 : la;
        int lr = l - 12; lr = lr < 0 ? 0 : lr;
        sum += xb[(la << 9) + d] - xb[(lr << 9) + d];
    }
}

// ---------------- special layernorm ----------------
__global__ void __launch_bounds__(256) ln_rows(const float* __restrict__ gam,
                                               const float* __restrict__ bet)
{
    int row = blockIdx.x;
    const float* xr = g_x + (long)row*512;
    int tid = threadIdx.x;
    float v0 = xr[tid], v1 = xr[tid+256];
    float s = v0 + v1, s2 = v0*v0 + v1*v1;
#pragma unroll
    for (int o = 16; o; o >>= 1) {
        s  += __shfl_down_sync(0xffffffffu, s,  o);
        s2 += __shfl_down_sync(0xffffffffu, s2, o);
    }
    __shared__ float sh1[8], sh2[8];
    __shared__ float mu_s, rs_s;
    int wid = tid >> 5, ln = tid & 31;
    if (!ln) { sh1[wid] = s; sh2[wid] = s2; }
    __syncthreads();
    if (tid == 0) {
        float S = 0.f, S2 = 0.f;
        for (int i = 0; i < 8; ++i) { S += sh1[i]; S2 += sh2[i]; }
        float mu = S * (1.f/512.f);
        float var = S2 * (1.f/512.f) - mu*mu;
        mu_s = mu; rs_s = rsqrtf(var + 1e-5f);
    }
    __syncthreads();
    float mu = mu_s, rs = rs_s;
    g_q[(long)row*512 + tid]       = (v0 - mu)*rs*gam[tid]     + bet[tid];
    g_q[(long)row*512 + tid + 256] = (v1 - mu)*rs*gam[tid+256] + bet[tid+256];
}

__global__ void colmean_k()
{
    int t = blockIdx.x*256 + threadIdx.x;
    int b = t >> 9, d = t & 511;
    const float* p = g_q + ((long)b << 19) + d;
    float s = 0.f;
    for (int l = 0; l < 1024; ++l) s += p[l << 9];
    g_colmean[t] = s * (1.f/1024.f);
}

__global__ void gelu_mask(const float* __restrict__ mark)
{
    int i = blockIdx.x*256 + threadIdx.x;
    int d = i & 511;
    int r = i >> 9;
    int b = r >> 10;
    float v = g_q[i] - g_colmean[(b << 9) + d];
    float g = 0.5f*v*(1.f + erff(v*0.70710678118654752f));
    g_k[i] = g * mark[r];
}

// ---------------- final projection (PSPLIT-way split-K) ----------------
__global__ void __launch_bounds__(256) proj_partial(const float* __restrict__ Wp)
{
    int ks = blockIdx.x;
    int tid = threadIdx.x;
    const int CH = LD/PSPLIT;      // 4096
    int wid = tid >> 5, ln = tid & 31;
    for (int n = 0; n < NCLS; ++n) {
        const float* wrow = Wp + (long)n*LD + (long)ks*CH;
        float acc[32];
#pragma unroll
        for (int b2 = 0; b2 < 32; ++b2) acc[b2] = 0.f;
        for (int k = tid; k < CH; k += 256) {
            float wv = wrow[k];
            long base = (long)ks*CH + k;
#pragma unroll
            for (int b2 = 0; b2 < 32; ++b2)
                acc[b2] = fmaf(wv, g_k[((long)b2 << 19) + base], acc[b2]);
        }
#pragma unroll
        for (int b2 = 0; b2 < 32; ++b2) {
            float v = acc[b2];
#pragma unroll
            for (int o = 16; o; o >>= 1) v += __shfl_down_sync(0xffffffffu, v, o);
            if (!ln) g_part[(((long)ks*NCLS + n)*8 + wid)*32 + b2] = v;
        }
    }
}

__global__ void proj_final(const float* __restrict__ bp, float* __restrict__ out)
{
    int t = threadIdx.x;
    if (t >= 32*NCLS) return;
    int b = t / NCLS, n = t % NCLS;
    float s = bp[n];
    for (int ks = 0; ks < PSPLIT; ++ks)
        for (int w = 0; w < 8; ++w)
            s += g_part[(((long)ks*NCLS + n)*8 + w)*32 + b];
    out[b*NCLS + n] = s;
}

// ---------------- host ----------------
extern "C" void kernel_launch(void* const* d_in, const int* in_sizes, int n_in,
                              void* d_out, int out_size)
{
    const float* x_enc   = (const float*)d_in[0];
    const float* x_mark  = (const float*)d_in[1];
    const float* conv_w  = (const float*)d_in[2];
    const float* Wq      = (const float*)d_in[3];
    const float* bq      = (const float*)d_in[4];
    const float* Wk      = (const float*)d_in[5];
    const float* Wv      = (const float*)d_in[7];
    const float* Wo      = (const float*)d_in[9];
    const float* bo      = (const float*)d_in[10];
    const float* Wff1    = (const float*)d_in[11];
    const float* Wff2    = (const float*)d_in[12];
    const float* ln_g    = (const float*)d_in[13];
    const float* ln_b    = (const float*)d_in[14];
    const float* Wproj   = (const float*)d_in[15];
    const float* bproj   = (const float*)d_in[16];
    float* out = (float*)d_out;

    float *px, *pq, *ptmp;
    bf16 *pcvA, *pcvB, *pcvH;
    cudaGetSymbolAddress((void**)&px,   g_x);
    cudaGetSymbolAddress((void**)&pq,   g_q);
    cudaGetSymbolAddress((void**)&ptmp, g_tmp);
    cudaGetSymbolAddress((void**)&pcvA, g_cvA);
    cudaGetSymbolAddress((void**)&pcvB, g_cvB);
    cudaGetSymbolAddress((void**)&pcvH, g_cvH);

    bf16* wqT_p = pcvB;
    bf16* wkT_p = pcvB + (size_t)512*1024;
    bf16* wvT_p = pcvB + (size_t)1024*1024;
    bf16* wo_p  = pcvB + (size_t)1536*1024;
    bf16* P_p   = pcvB + (size_t)2048*1024;
    bf16* NN_p  = pcvB + (size_t)2560*1024;
    bf16* w1_p  = pcvB;                          // reuse after a-GEMM
    bf16* w2_p  = pcvB + (size_t)2048*1024;      // reuse after a-GEMM

    cudaFuncSetAttribute(gemm_mma<0>, cudaFuncAttributeMaxDynamicSharedMemorySize, GSMEM);
    cudaFuncSetAttribute(gemm_mma<1>, cudaFuncAttributeMaxDynamicSharedMemorySize, GSMEM);
    cudaFuncSetAttribute(gemm_mma<2>, cudaFuncAttributeMaxDynamicSharedMemorySize, GSMEM);
    cudaFuncSetAttribute(gemm_mma<3>, cudaFuncAttributeMaxDynamicSharedMemorySize, GSMEM);
    cudaFuncSetAttribute(gemm_small2, cudaFuncAttributeMaxDynamicSharedMemorySize, GSMEM);

    conv_embed<<<dim3(BATCH, SEQL/16), 512>>>(x_enc, conv_w);

    for (int l = 0; l < NLAYERS; ++l) {
        const float* wq = Wq + (long)l*DMODEL*DMODEL;
        const float* wk = Wk + (long)l*DMODEL*DMODEL;
        const float* wv = Wv + (long)l*DMODEL*DMODEL;
        const float* wo = Wo + (long)l*DMODEL*DMODEL;
        const float* w1 = Wff1 + (long)l*DFF*DMODEL;
        const float* w2 = Wff2 + (long)l*DMODEL*DFF;

        // all four attention weight conversions in one launch
        wprep4<<<dim3(16,16,4), dim3(32,8)>>>(wq, wqT_p, wk, wkT_p, wv, wvT_p, wo, wo_p);
        // P = Wk^T·Wq and NN = Wo·Wv in one launch
        gemm_small2<<<dim3(4,4,2), 256, GSMEM>>>(wkT_p, wqT_p, P_p, wo_p, wvT_p, NN_p);

        // y = x @ P^T  (corr surrogate; bq zeros)
        gemm_mma<0><<<dim3(DMODEL/128, BL/128), 256, GSMEM>>>(pcvA, P_p, bq + l*DMODEL, nullptr, pq, nullptr, DMODEL, DMODEL);

        // autocorrelation: S = sum_d Yf * conj(Xf)
        transpose_qk<<<dim3(DMODEL/32, SEQL/32, BATCH*2), dim3(32, 8)>>>();
        fft_corr<<<dim3(32, BATCH), 256>>>();
        reduce_S<<<dim3(BATCH, 4), 256>>>();
        ifft_mv<<<BATCH, 256>>>();
        topk_softmax<<<BATCH, 256>>>();
        aggregate<<<(BL*DMODEL)/256, 256>>>();

        // a = xs @ NN^T + bo + x -> g_tmp ; then decomp
        gemm_mma<1><<<dim3(DMODEL/128, BL/128), 256, GSMEM>>>(pcvA, NN_p, bo + l*DMODEL, px, ptmp, nullptr, DMODEL, DMODEL);
        decomp<<<(BATCH*DMODEL*8)/256, 256>>>();

        // FFN
        cvt_pair_w<<<(DFF*DMODEL+255)/256, 256>>>(w1, w1_p, DMODEL, DFF*DMODEL);
        gemm_mma<2><<<dim3(DFF/128, BL/128), 256, GSMEM>>>(pcvA, w1_p, nullptr, nullptr, nullptr, pcvH, DFF, DMODEL);
        cvt_pair_w<<<(DMODEL*DFF+255)/256, 256>>>(w2, w2_p, DFF, DMODEL*DFF);
        gemm_mma<3><<<dim3(DMODEL/128, BL/128), 256, GSMEM>>>(pcvH, w2_p, nullptr, px, ptmp, nullptr, DMODEL, DFF);
        decomp<<<(BATCH*DMODEL*8)/256, 256>>>();
    }

    ln_rows<<<BL, 256>>>(ln_g, ln_b);
    colmean_k<<<(BATCH*DMODEL)/256, 256>>>();
    gelu_mask<<<(BL*DMODEL)/256, 256>>>(x_mark);
    proj_partial<<<PSPLIT, 256>>>(Wproj);
    proj_final<<<1, 512>>>(bproj, out);
}